// round 7
// baseline (speedup 1.0000x reference)
#include <cuda_runtime.h>
#include <cuda_bf16.h>
#include <cstdint>
#include <cstddef>

// Problem constants
#define B_    8
#define N_    1024
#define DIM_  768
#define HEADS 12
#define DH    64
#define INNER 768          // HEADS*DH
#define QKV3  2304         // 3*INNER
#define SCALE 0.125f       // DH^-0.5

// Scratch (device globals: allocation-free rule)
__device__ float g_qkv[(size_t)B_ * N_ * QKV3];   // [b, n, 3*inner]
__device__ float g_att[(size_t)B_ * N_ * INNER];  // [b, n, h*DH+d]

// ---------------------------------------------------------------------------
// tf32 helpers
// ---------------------------------------------------------------------------
__device__ __forceinline__ uint32_t f2tf32(float x) {
    uint32_t u;
    asm("cvt.rna.tf32.f32 %0, %1;" : "=r"(u) : "f"(x));
    return u;
}
__device__ __forceinline__ float f2tf32f(float x) {
    return __uint_as_float(f2tf32(x));
}

__device__ __forceinline__ void mma_tf32(float c[4], const uint32_t a[4],
                                         uint32_t b0, uint32_t b1) {
    asm volatile(
        "mma.sync.aligned.m16n8k8.row.col.f32.tf32.tf32.f32 "
        "{%0,%1,%2,%3}, {%4,%5,%6,%7}, {%8,%9}, {%0,%1,%2,%3};"
        : "+f"(c[0]), "+f"(c[1]), "+f"(c[2]), "+f"(c[3])
        : "r"(a[0]), "r"(a[1]), "r"(a[2]), "r"(a[3]), "r"(b0), "r"(b1));
}

// ---------------------------------------------------------------------------
// tf32 GEMM, fragment-permuted smem. C[M,N] = A[M,K]*B[K,N].
// Block: 128 thr (4 warps, 2x2), tile 128x128x32, warp tile 64x64.
// Aperm: combo(m16,kc) * 128 + lane*4 + reg        (LDS.128 per A frag)
// Bperm: combo(n8,kc)  * 64  + lane*2 + half      (LDS.64  per B frag)
// ---------------------------------------------------------------------------
__global__ __launch_bounds__(128) void gemm_tf32_kernel(
    const float* __restrict__ A, const float* __restrict__ Bm,
    float* __restrict__ C, int M, int N, int K)
{
    __shared__ float Aperm[8 * 4 * 128];   // 16 KB
    __shared__ float Bperm[16 * 4 * 64];   // 16 KB

    const int tid = threadIdx.x;
    const int warpid = tid >> 5;
    const int lane = tid & 31;
    const int g   = lane >> 2;
    const int tig = lane & 3;

    const int row0 = blockIdx.y * 128;
    const int col0 = blockIdx.x * 128;
    const int wm16 = (warpid >> 1) * 4;   // warp's first m16 block (0 or 4)
    const int wn8  = (warpid & 1) * 8;    // warp's first n8 block (0 or 8)

    float acc[4][8][4];
    #pragma unroll
    for (int mi = 0; mi < 4; mi++)
        #pragma unroll
        for (int j = 0; j < 8; j++)
            #pragma unroll
            for (int r = 0; r < 4; r++) acc[mi][j][r] = 0.f;

    for (int k0 = 0; k0 < K; k0 += 32) {
        // ---- A tile 128x32 -> Aperm (8 float4 per thread) ----
        #pragma unroll
        for (int i = 0; i < 8; i++) {
            int idx = tid + i * 128;
            int r = idx >> 3, cg = idx & 7;
            float4 v = *(const float4*)&A[(size_t)(row0 + r) * K + k0 + cg * 4];
            int m16 = r >> 4, ga = r & 7, hi = (r >> 3) & 1;
            int kc = cg >> 1, halfk = cg & 1;
            int slot = hi + 2 * halfk;
            float* dst = &Aperm[((m16 * 4 + kc) << 7) + (ga << 4) + slot];
            dst[0]  = f2tf32f(v.x);
            dst[4]  = f2tf32f(v.y);
            dst[8]  = f2tf32f(v.z);
            dst[12] = f2tf32f(v.w);
        }
        // ---- B tile 32x128 -> Bperm (8 float4 per thread) ----
        #pragma unroll
        for (int i = 0; i < 8; i++) {
            int idx = tid + i * 128;
            int r = idx >> 5, cg = idx & 31;
            float4 v = *(const float4*)&Bm[(size_t)(k0 + r) * N + col0 + cg * 4];
            int kc = r >> 3, tb = r & 3, halfk = (r >> 2) & 1;
            int n8 = cg >> 1, g0 = (cg & 1) * 4;
            float* dst = &Bperm[((n8 * 4 + kc) * 32 + g0 * 4 + tb) * 2 + halfk];
            dst[0]  = f2tf32f(v.x);
            dst[8]  = f2tf32f(v.y);
            dst[16] = f2tf32f(v.z);
            dst[24] = f2tf32f(v.w);
        }
        __syncthreads();

        #pragma unroll
        for (int kc = 0; kc < 4; kc++) {
            uint32_t a[4][4];
            #pragma unroll
            for (int mi = 0; mi < 4; mi++) {
                float4 af = *(const float4*)
                    &Aperm[(((wm16 + mi) * 4 + kc) << 7) + (lane << 2)];
                a[mi][0] = __float_as_uint(af.x);
                a[mi][1] = __float_as_uint(af.y);
                a[mi][2] = __float_as_uint(af.z);
                a[mi][3] = __float_as_uint(af.w);
            }
            #pragma unroll
            for (int j = 0; j < 8; j++) {
                float2 bf = *(const float2*)
                    &Bperm[(((wn8 + j) * 4 + kc) * 32 + lane) * 2];
                uint32_t b0 = __float_as_uint(bf.x);
                uint32_t b1 = __float_as_uint(bf.y);
                #pragma unroll
                for (int mi = 0; mi < 4; mi++)
                    mma_tf32(acc[mi][j], a[mi], b0, b1);
            }
        }
        __syncthreads();
    }

    // Writeback
    #pragma unroll
    for (int mi = 0; mi < 4; mi++) {
        int r0 = row0 + (wm16 + mi) * 16 + g;
        #pragma unroll
        for (int j = 0; j < 8; j++) {
            int col = col0 + (wn8 + j) * 8 + 2 * tig;
            *(float2*)&C[(size_t)r0 * N + col] =
                make_float2(acc[mi][j][0], acc[mi][j][1]);
            *(float2*)&C[(size_t)(r0 + 8) * N + col] =
                make_float2(acc[mi][j][2], acc[mi][j][3]);
        }
    }
}

// ---------------------------------------------------------------------------
// Fused shuffled-Q flash attention, tf32 MMA, permuted fragment smem.
// Block 256 thr (8 warps), q-tile 128 rows (16 per warp), K/V tiles 64.
// Grid: (B*HEADS, N/128).
// smem: QPs[8704] (Q staging 128x68, then per-warp Pperm[kc=8][lane*4+reg])
//       Kp: combo(j,kc)*64 + lane*2 + half   (4096 floats)
//       Vp: combo(j,kc)*64 + lane*2 + half   (4096 floats)
// ---------------------------------------------------------------------------
#define QST 68
#define ATTN_SMEM ((8704 + 4096 + 4096) * sizeof(float))   // 67584 B

__global__ __launch_bounds__(256) void attn_kernel(
    const float* __restrict__ qkv, const int* __restrict__ perm,
    float* __restrict__ out)
{
    extern __shared__ float sm[];
    float* QPs = sm;                 // staging then Pperm
    float* Kp  = sm + 8704;
    float* Vp  = sm + 8704 + 4096;

    const int bh = blockIdx.x;
    const int b  = bh / HEADS, h = bh % HEADS;
    const int qt = blockIdx.y;
    const int tid = threadIdx.x;
    const int w    = tid >> 5;
    const int lane = tid & 31;
    const int g   = lane >> 2;
    const int tig = lane & 3;
    const int wq  = w * 16;

    const float* base = qkv + (size_t)b * N_ * QKV3;

    // ---- Stage shuffled Q tile (perm gather), tf32-converted ----
    #pragma unroll
    for (int i = 0; i < 32; i++) {
        int idx = tid + i * 256;            // 0..8191
        int r = idx >> 6, d = idx & 63;
        int p  = perm[((qt * 128 + r) << 6) + d];
        int n2 = p >> 6, d2 = p & 63;
        QPs[r * QST + d] = f2tf32f(base[(size_t)n2 * QKV3 + h * DH + d2]);
    }
    __syncthreads();

    // ---- Cache Q fragments in registers (whole key loop) ----
    uint32_t qa[8][4];
    #pragma unroll
    for (int kc = 0; kc < 8; kc++) {
        int r = wq + g;
        qa[kc][0] = __float_as_uint(QPs[r * QST + kc * 8 + tig]);
        qa[kc][1] = __float_as_uint(QPs[(r + 8) * QST + kc * 8 + tig]);
        qa[kc][2] = __float_as_uint(QPs[r * QST + kc * 8 + tig + 4]);
        qa[kc][3] = __float_as_uint(QPs[(r + 8) * QST + kc * 8 + tig + 4]);
    }

    float* Pw = QPs + w * 1024;   // this warp's Pperm region (aliases staging)

    float o[8][4];
    #pragma unroll
    for (int j = 0; j < 8; j++)
        #pragma unroll
        for (int r = 0; r < 4; r++) o[j][r] = 0.f;
    float m0 = -1e30f, m1 = -1e30f, l0 = 0.f, l1 = 0.f;

    for (int kt = 0; kt < N_ / 64; kt++) {
        __syncthreads();   // staging/Q-frag reads + prior-tile K/V reads done
        // ---- Load K,V tiles (64 keys x 64 d) into permuted layouts ----
        #pragma unroll
        for (int i = 0; i < 4; i++) {
            int idx = tid + i * 256;        // 0..1023 float4 slots
            int key = idx >> 4, d4 = idx & 15;
            const float* rowp = base + (size_t)(kt * 64 + key) * QKV3 + h * DH;
            float4 kv = *(const float4*)(rowp + INNER + d4 * 4);
            float4 vv = *(const float4*)(rowp + 2 * INNER + d4 * 4);
            // K (B-frag of QK^T): combo=(j=key>>3, kc=d>>3); lane=(g=key&7, t=d&3)
            {
                int jj = key >> 3, gk = key & 7;
                int kc = d4 >> 1, half = d4 & 1;
                float* dst = &Kp[((jj * 8 + kc) * 32 + gk * 4) * 2 + half];
                dst[0] = f2tf32f(kv.x);
                dst[2] = f2tf32f(kv.y);
                dst[4] = f2tf32f(kv.z);
                dst[6] = f2tf32f(kv.w);
            }
            // V (B-frag of P@V): combo=(j=d>>3, kc=key>>3); lane=(g=d&7, t=key&3)
            {
                int kc = key >> 3, tv = key & 3, half = (key >> 2) & 1;
                int jj = d4 >> 1, g0 = (d4 & 1) * 4;
                float* dst = &Vp[((jj * 8 + kc) * 32 + g0 * 4 + tv) * 2 + half];
                dst[0]  = f2tf32f(vv.x);
                dst[8]  = f2tf32f(vv.y);
                dst[16] = f2tf32f(vv.z);
                dst[24] = f2tf32f(vv.w);
            }
        }
        __syncthreads();

        // ---- S = Q K^T : m16 x n64, 8 k8-steps, A from registers ----
        float s[8][4];
        #pragma unroll
        for (int j = 0; j < 8; j++)
            #pragma unroll
            for (int r = 0; r < 4; r++) s[j][r] = 0.f;
        #pragma unroll
        for (int kc = 0; kc < 8; kc++) {
            #pragma unroll
            for (int j = 0; j < 8; j++) {
                float2 bf = *(const float2*)&Kp[((j * 8 + kc) * 32 + lane) * 2];
                mma_tf32(s[j], qa[kc],
                         __float_as_uint(bf.x), __float_as_uint(bf.y));
            }
        }

        // ---- Online softmax (rows g / g+8 within warp's 16) ----
        float mx0 = -1e30f, mx1 = -1e30f;
        #pragma unroll
        for (int j = 0; j < 8; j++) {
            s[j][0] *= SCALE; s[j][1] *= SCALE; s[j][2] *= SCALE; s[j][3] *= SCALE;
            mx0 = fmaxf(mx0, fmaxf(s[j][0], s[j][1]));
            mx1 = fmaxf(mx1, fmaxf(s[j][2], s[j][3]));
        }
        mx0 = fmaxf(mx0, __shfl_xor_sync(0xffffffffu, mx0, 1));
        mx0 = fmaxf(mx0, __shfl_xor_sync(0xffffffffu, mx0, 2));
        mx1 = fmaxf(mx1, __shfl_xor_sync(0xffffffffu, mx1, 1));
        mx1 = fmaxf(mx1, __shfl_xor_sync(0xffffffffu, mx1, 2));

        float nm0 = fmaxf(m0, mx0), nm1 = fmaxf(m1, mx1);
        float al0 = __expf(m0 - nm0), al1 = __expf(m1 - nm1);
        float rs0 = 0.f, rs1 = 0.f;
        // P store offsets (A-frag order): key = j*8 + 2*tig + e
        int t8a = 2 * tig,      ta = t8a & 3, ha = t8a >> 2;
        int t8b = 2 * tig + 1,  tb = t8b & 3, hb = t8b >> 2;
        #pragma unroll
        for (int j = 0; j < 8; j++) {
            s[j][0] = __expf(s[j][0] - nm0);
            s[j][1] = __expf(s[j][1] - nm0);
            s[j][2] = __expf(s[j][2] - nm1);
            s[j][3] = __expf(s[j][3] - nm1);
            rs0 += s[j][0] + s[j][1];
            rs1 += s[j][2] + s[j][3];
            float* pj = &Pw[(j << 7) + (g << 4)];
            pj[ta * 4 + 2 * ha + 0] = f2tf32f(s[j][0]);
            pj[tb * 4 + 2 * hb + 0] = f2tf32f(s[j][1]);
            pj[ta * 4 + 2 * ha + 1] = f2tf32f(s[j][2]);
            pj[tb * 4 + 2 * hb + 1] = f2tf32f(s[j][3]);
        }
        rs0 += __shfl_xor_sync(0xffffffffu, rs0, 1);
        rs0 += __shfl_xor_sync(0xffffffffu, rs0, 2);
        rs1 += __shfl_xor_sync(0xffffffffu, rs1, 1);
        rs1 += __shfl_xor_sync(0xffffffffu, rs1, 2);
        l0 = l0 * al0 + rs0; l1 = l1 * al1 + rs1;
        m0 = nm0; m1 = nm1;
        #pragma unroll
        for (int j = 0; j < 8; j++) {
            o[j][0] *= al0; o[j][1] *= al0; o[j][2] *= al1; o[j][3] *= al1;
        }
        __syncwarp();   // Pperm is warp-private

        // ---- O += P V : m16 x n64, 8 k8-steps ----
        #pragma unroll
        for (int kc = 0; kc < 8; kc++) {
            uint32_t pa[4];
            float4 pf = *(const float4*)&Pw[(kc << 7) + (lane << 2)];
            pa[0] = __float_as_uint(pf.x);
            pa[1] = __float_as_uint(pf.y);
            pa[2] = __float_as_uint(pf.z);
            pa[3] = __float_as_uint(pf.w);
            #pragma unroll
            for (int j = 0; j < 8; j++) {
                float2 bf = *(const float2*)&Vp[((j * 8 + kc) * 32 + lane) * 2];
                mma_tf32(o[j], pa,
                         __float_as_uint(bf.x), __float_as_uint(bf.y));
            }
        }
        __syncwarp();
    }

    // ---- Normalize + write out[b, q, h*DH + d] ----
    float inv0 = 1.0f / l0, inv1 = 1.0f / l1;
    int q0 = qt * 128 + wq + g;
    #pragma unroll
    for (int j = 0; j < 8; j++) {
        int d = j * 8 + 2 * tig;
        size_t o0 = ((size_t)b * N_ + q0) * INNER + h * DH + d;
        size_t o1 = ((size_t)b * N_ + q0 + 8) * INNER + h * DH + d;
        *(float2*)&out[o0] = make_float2(o[j][0] * inv0, o[j][1] * inv0);
        *(float2*)&out[o1] = make_float2(o[j][2] * inv1, o[j][3] * inv1);
    }
}

// ---------------------------------------------------------------------------
// Launch
// ---------------------------------------------------------------------------
extern "C" void kernel_launch(void* const* d_in, const int* in_sizes, int n_in,
                              void* d_out, int out_size)
{
    const float* x    = (const float*)d_in[0];   // [8,1024,768]
    const float* Wqkv = (const float*)d_in[1];   // [768,2304]
    const float* Wout = (const float*)d_in[2];   // [768,768]
    const int*   perm = (const int*)d_in[3];     // [65536]
    float* out = (float*)d_out;

    float *qkv, *att;
    cudaGetSymbolAddress((void**)&qkv, g_qkv);
    cudaGetSymbolAddress((void**)&att, g_att);
    cudaFuncSetAttribute(attn_kernel,
                         cudaFuncAttributeMaxDynamicSharedMemorySize,
                         (int)ATTN_SMEM);

    const int M = B_ * N_;  // 8192

    // 1) QKV projection
    gemm_tf32_kernel<<<dim3(QKV3 / 128, M / 128), 128>>>(x, Wqkv, qkv, M, QKV3, DIM_);
    // 2) Shuffled-Q attention (perm gather fused into Q load)
    attn_kernel<<<dim3(B_ * HEADS, N_ / 128), 256, ATTN_SMEM>>>(qkv, perm, att);
    // 3) Output projection
    gemm_tf32_kernel<<<dim3(INNER / 128, M / 128), 128>>>(att, Wout, out, M, INNER, DIM_);
}

// round 9
// speedup vs baseline: 2.0303x; 2.0303x over previous
#include <cuda_runtime.h>
#include <cuda_bf16.h>
#include <cstdint>
#include <cstddef>

// Problem constants
#define B_    8
#define N_    1024
#define DIM_  768
#define HEADS 12
#define DH    64
#define INNER 768          // HEADS*DH
#define QKV3  2304         // 3*INNER
#define SCALE 0.125f       // DH^-0.5

// Scratch (device globals: allocation-free rule)
__device__ float g_qkv[(size_t)B_ * N_ * QKV3];   // [b, n, 3*inner]
__device__ float g_att[(size_t)B_ * N_ * INNER];  // [b, n, h*DH+d]

// ---------------------------------------------------------------------------
// tf32 helpers
// ---------------------------------------------------------------------------
__device__ __forceinline__ uint32_t f2tf32(float x) {
    uint32_t u;
    asm("cvt.rna.tf32.f32 %0, %1;" : "=r"(u) : "f"(x));
    return u;
}
__device__ __forceinline__ float f2tf32f(float x) {
    return __uint_as_float(f2tf32(x));
}

__device__ __forceinline__ void mma_tf32(float c[4], const uint32_t a[4],
                                         uint32_t b0, uint32_t b1) {
    asm volatile(
        "mma.sync.aligned.m16n8k8.row.col.f32.tf32.tf32.f32 "
        "{%0,%1,%2,%3}, {%4,%5,%6,%7}, {%8,%9}, {%0,%1,%2,%3};"
        : "+f"(c[0]), "+f"(c[1]), "+f"(c[2]), "+f"(c[3])
        : "r"(a[0]), "r"(a[1]), "r"(a[2]), "r"(a[3]), "r"(b0), "r"(b1));
}

// ---------------------------------------------------------------------------
// tf32 GEMM: C[M,N] = A[M,K]*B[K,N], padded row-major smem (conflict-free).
// Block 256 thr (8 warps, 4x2), tile 256x128x32, warp tile 64x64.
// As[m][k] stride 36, Bs[k][n] stride 136. Reads: bank(A)=4g+tig,
// bank(B)=8*tig+g — full permutations, conflict-free.
// ---------------------------------------------------------------------------
#define ASTR 36
#define BSTR 136
#define GEMM_SMEM ((256 * ASTR + 32 * BSTR) * sizeof(float))   // 54272 B

__global__ __launch_bounds__(256, 1) void gemm_tf32_kernel(
    const float* __restrict__ A, const float* __restrict__ Bm,
    float* __restrict__ C, int M, int N, int K)
{
    extern __shared__ float gsm[];
    float* As = gsm;                // [256][ASTR]
    float* Bs = gsm + 256 * ASTR;   // [32][BSTR]

    const int tid = threadIdx.x;
    const int warpid = tid >> 5;
    const int lane = tid & 31;
    const int g   = lane >> 2;
    const int tig = lane & 3;

    const int row0 = blockIdx.y * 256;
    const int col0 = blockIdx.x * 128;
    const int wm = (warpid >> 1) * 64;   // 4 m-warps
    const int wn = (warpid & 1) * 64;    // 2 n-warps

    float acc[4][8][4];
    #pragma unroll
    for (int mi = 0; mi < 4; mi++)
        #pragma unroll
        for (int j = 0; j < 8; j++)
            #pragma unroll
            for (int r = 0; r < 4; r++) acc[mi][j][r] = 0.f;

    for (int k0 = 0; k0 < K; k0 += 32) {
        // A tile 256x32: 2048 float4, 8 per thread
        #pragma unroll
        for (int i = 0; i < 8; i++) {
            int idx = tid + i * 256;
            int r = idx >> 3, cg = idx & 7;
            float4 v = *(const float4*)&A[(size_t)(row0 + r) * K + k0 + cg * 4];
            float* dst = &As[r * ASTR + cg * 4];
            dst[0] = f2tf32f(v.x);
            dst[1] = f2tf32f(v.y);
            dst[2] = f2tf32f(v.z);
            dst[3] = f2tf32f(v.w);
        }
        // B tile 32x128: 1024 float4, 4 per thread
        #pragma unroll
        for (int i = 0; i < 4; i++) {
            int idx = tid + i * 256;
            int r = idx >> 5, cg = idx & 31;
            float4 v = *(const float4*)&Bm[(size_t)(k0 + r) * N + col0 + cg * 4];
            float* dst = &Bs[r * BSTR + cg * 4];
            dst[0] = f2tf32f(v.x);
            dst[1] = f2tf32f(v.y);
            dst[2] = f2tf32f(v.z);
            dst[3] = f2tf32f(v.w);
        }
        __syncthreads();

        #pragma unroll
        for (int kc = 0; kc < 4; kc++) {
            uint32_t a[4][4];
            #pragma unroll
            for (int mi = 0; mi < 4; mi++) {
                int r = wm + mi * 16 + g;
                a[mi][0] = __float_as_uint(As[r * ASTR + kc * 8 + tig]);
                a[mi][1] = __float_as_uint(As[(r + 8) * ASTR + kc * 8 + tig]);
                a[mi][2] = __float_as_uint(As[r * ASTR + kc * 8 + tig + 4]);
                a[mi][3] = __float_as_uint(As[(r + 8) * ASTR + kc * 8 + tig + 4]);
            }
            #pragma unroll
            for (int j = 0; j < 8; j++) {
                uint32_t b0 = __float_as_uint(Bs[(kc * 8 + tig) * BSTR + wn + j * 8 + g]);
                uint32_t b1 = __float_as_uint(Bs[(kc * 8 + tig + 4) * BSTR + wn + j * 8 + g]);
                #pragma unroll
                for (int mi = 0; mi < 4; mi++)
                    mma_tf32(acc[mi][j], a[mi], b0, b1);
            }
        }
        __syncthreads();
    }

    // Writeback
    #pragma unroll
    for (int mi = 0; mi < 4; mi++) {
        int r0 = row0 + wm + mi * 16 + g;
        #pragma unroll
        for (int j = 0; j < 8; j++) {
            int col = col0 + wn + j * 8 + 2 * tig;
            *(float2*)&C[(size_t)r0 * N + col] =
                make_float2(acc[mi][j][0], acc[mi][j][1]);
            *(float2*)&C[(size_t)(r0 + 8) * N + col] =
                make_float2(acc[mi][j][2], acc[mi][j][3]);
        }
    }
}

// ---------------------------------------------------------------------------
// Fused shuffled-Q flash attention, tf32 MMA, padded smem (Round-4 layout).
// Block 256 thr (8 warps), q-tile 128 rows (16/warp), K/V tiles 64 keys.
// Q fragments register-cached for the whole key loop; Ps aliases Q staging.
// Grid: (B*HEADS, N/128).
// ---------------------------------------------------------------------------
#define AST 68
#define ATTN_SMEM ((128 * AST + 64 * AST + 64 * AST) * sizeof(float))  // 69632 B

__global__ __launch_bounds__(256) void attn_kernel(
    const float* __restrict__ qkv, const int* __restrict__ perm,
    float* __restrict__ out)
{
    extern __shared__ float sm[];
    float* Qs = sm;                   // [128][AST] staging, then Ps
    float* Ks = sm + 128 * AST;       // [64][AST]
    float* Vs = sm + 192 * AST;       // [64][AST]
    float* Ps = Qs;                   // alias: Q lives in regs after prologue

    const int bh = blockIdx.x;
    const int b  = bh / HEADS, h = bh % HEADS;
    const int qt = blockIdx.y;
    const int tid = threadIdx.x;
    const int w    = tid >> 5;
    const int lane = tid & 31;
    const int g   = lane >> 2;
    const int tig = lane & 3;
    const int wq  = w * 16;

    const float* base = qkv + (size_t)b * N_ * QKV3;

    // ---- Stage shuffled Q tile (perm gather), tf32-converted ----
    #pragma unroll
    for (int i = 0; i < 32; i++) {
        int idx = tid + i * 256;            // 0..8191
        int r = idx >> 6, d = idx & 63;
        int p  = perm[((qt * 128 + r) << 6) + d];
        int n2 = p >> 6, d2 = p & 63;
        Qs[r * AST + d] = f2tf32f(base[(size_t)n2 * QKV3 + h * DH + d2]);
    }
    __syncthreads();

    // ---- Cache Q fragments in registers (whole key loop) ----
    uint32_t qa[8][4];
    #pragma unroll
    for (int kc = 0; kc < 8; kc++) {
        int r = wq + g;
        qa[kc][0] = __float_as_uint(Qs[r * AST + kc * 8 + tig]);
        qa[kc][1] = __float_as_uint(Qs[(r + 8) * AST + kc * 8 + tig]);
        qa[kc][2] = __float_as_uint(Qs[r * AST + kc * 8 + tig + 4]);
        qa[kc][3] = __float_as_uint(Qs[(r + 8) * AST + kc * 8 + tig + 4]);
    }

    float o[8][4];
    #pragma unroll
    for (int j = 0; j < 8; j++)
        #pragma unroll
        for (int r = 0; r < 4; r++) o[j][r] = 0.f;
    float m0 = -1e30f, m1 = -1e30f, l0 = 0.f, l1 = 0.f;

    for (int kt = 0; kt < N_ / 64; kt++) {
        __syncthreads();   // all warps done reading Qs / prior K,V tiles
        // ---- Load K,V tiles (64 keys x 64 d), padded rows ----
        #pragma unroll
        for (int i = 0; i < 4; i++) {
            int idx = tid + i * 256;        // 0..1023 float4 slots
            int key = idx >> 4, d4 = idx & 15;
            const float* rowp = base + (size_t)(kt * 64 + key) * QKV3 + h * DH;
            float4 kv = *(const float4*)(rowp + INNER + d4 * 4);
            float4 vv = *(const float4*)(rowp + 2 * INNER + d4 * 4);
            float* kd = &Ks[key * AST + d4 * 4];
            float* vd = &Vs[key * AST + d4 * 4];
            kd[0] = f2tf32f(kv.x);
            kd[1] = f2tf32f(kv.y);
            kd[2] = f2tf32f(kv.z);
            kd[3] = f2tf32f(kv.w);
            vd[0] = f2tf32f(vv.x);
            vd[1] = f2tf32f(vv.y);
            vd[2] = f2tf32f(vv.z);
            vd[3] = f2tf32f(vv.w);
        }
        __syncthreads();

        // ---- S = Q K^T : m16 x n64, 8 k8-steps, A from registers ----
        float s[8][4];
        #pragma unroll
        for (int j = 0; j < 8; j++)
            #pragma unroll
            for (int r = 0; r < 4; r++) s[j][r] = 0.f;
        #pragma unroll
        for (int kc = 0; kc < 8; kc++) {
            #pragma unroll
            for (int j = 0; j < 8; j++) {
                uint32_t b0 = __float_as_uint(Ks[(j * 8 + g) * AST + kc * 8 + tig]);
                uint32_t b1 = __float_as_uint(Ks[(j * 8 + g) * AST + kc * 8 + tig + 4]);
                mma_tf32(s[j], qa[kc], b0, b1);
            }
        }

        // ---- Online softmax (rows g / g+8 within warp's 16) ----
        float mx0 = -1e30f, mx1 = -1e30f;
        #pragma unroll
        for (int j = 0; j < 8; j++) {
            s[j][0] *= SCALE; s[j][1] *= SCALE; s[j][2] *= SCALE; s[j][3] *= SCALE;
            mx0 = fmaxf(mx0, fmaxf(s[j][0], s[j][1]));
            mx1 = fmaxf(mx1, fmaxf(s[j][2], s[j][3]));
        }
        mx0 = fmaxf(mx0, __shfl_xor_sync(0xffffffffu, mx0, 1));
        mx0 = fmaxf(mx0, __shfl_xor_sync(0xffffffffu, mx0, 2));
        mx1 = fmaxf(mx1, __shfl_xor_sync(0xffffffffu, mx1, 1));
        mx1 = fmaxf(mx1, __shfl_xor_sync(0xffffffffu, mx1, 2));

        float nm0 = fmaxf(m0, mx0), nm1 = fmaxf(m1, mx1);
        float al0 = __expf(m0 - nm0), al1 = __expf(m1 - nm1);
        float rs0 = 0.f, rs1 = 0.f;
        #pragma unroll
        for (int j = 0; j < 8; j++) {
            s[j][0] = __expf(s[j][0] - nm0);
            s[j][1] = __expf(s[j][1] - nm0);
            s[j][2] = __expf(s[j][2] - nm1);
            s[j][3] = __expf(s[j][3] - nm1);
            rs0 += s[j][0] + s[j][1];
            rs1 += s[j][2] + s[j][3];
            int pr = wq + g;
            int pc = j * 8 + 2 * tig;
            *(float2*)&Ps[pr * AST + pc] = make_float2(
                f2tf32f(s[j][0]), f2tf32f(s[j][1]));
            *(float2*)&Ps[(pr + 8) * AST + pc] = make_float2(
                f2tf32f(s[j][2]), f2tf32f(s[j][3]));
        }
        rs0 += __shfl_xor_sync(0xffffffffu, rs0, 1);
        rs0 += __shfl_xor_sync(0xffffffffu, rs0, 2);
        rs1 += __shfl_xor_sync(0xffffffffu, rs1, 1);
        rs1 += __shfl_xor_sync(0xffffffffu, rs1, 2);
        l0 = l0 * al0 + rs0; l1 = l1 * al1 + rs1;
        m0 = nm0; m1 = nm1;
        #pragma unroll
        for (int j = 0; j < 8; j++) {
            o[j][0] *= al0; o[j][1] *= al0; o[j][2] *= al1; o[j][3] *= al1;
        }
        __syncwarp();   // Ps rows are warp-private (wq..wq+15)

        // ---- O += P V : m16 x n64, 8 k8-steps ----
        #pragma unroll
        for (int kc = 0; kc < 8; kc++) {
            uint32_t pa[4];
            int r = wq + g;
            pa[0] = __float_as_uint(Ps[r * AST + kc * 8 + tig]);
            pa[1] = __float_as_uint(Ps[(r + 8) * AST + kc * 8 + tig]);
            pa[2] = __float_as_uint(Ps[r * AST + kc * 8 + tig + 4]);
            pa[3] = __float_as_uint(Ps[(r + 8) * AST + kc * 8 + tig + 4]);
            #pragma unroll
            for (int j = 0; j < 8; j++) {
                uint32_t b0 = __float_as_uint(Vs[(kc * 8 + tig) * AST + j * 8 + g]);
                uint32_t b1 = __float_as_uint(Vs[(kc * 8 + tig + 4) * AST + j * 8 + g]);
                mma_tf32(o[j], pa, b0, b1);
            }
        }
        __syncwarp();
    }

    // ---- Normalize + write out[b, q, h*DH + d] ----
    float inv0 = 1.0f / l0, inv1 = 1.0f / l1;
    int q0 = qt * 128 + wq + g;
    #pragma unroll
    for (int j = 0; j < 8; j++) {
        int d = j * 8 + 2 * tig;
        size_t o0 = ((size_t)b * N_ + q0) * INNER + h * DH + d;
        size_t o1 = ((size_t)b * N_ + q0 + 8) * INNER + h * DH + d;
        *(float2*)&out[o0] = make_float2(o[j][0] * inv0, o[j][1] * inv0);
        *(float2*)&out[o1] = make_float2(o[j][2] * inv1, o[j][3] * inv1);
    }
}

// ---------------------------------------------------------------------------
// Launch
// ---------------------------------------------------------------------------
extern "C" void kernel_launch(void* const* d_in, const int* in_sizes, int n_in,
                              void* d_out, int out_size)
{
    const float* x    = (const float*)d_in[0];   // [8,1024,768]
    const float* Wqkv = (const float*)d_in[1];   // [768,2304]
    const float* Wout = (const float*)d_in[2];   // [768,768]
    const int*   perm = (const int*)d_in[3];     // [65536]
    float* out = (float*)d_out;

    float *qkv, *att;
    cudaGetSymbolAddress((void**)&qkv, g_qkv);
    cudaGetSymbolAddress((void**)&att, g_att);
    cudaFuncSetAttribute(gemm_tf32_kernel,
                         cudaFuncAttributeMaxDynamicSharedMemorySize,
                         (int)GEMM_SMEM);
    cudaFuncSetAttribute(attn_kernel,
                         cudaFuncAttributeMaxDynamicSharedMemorySize,
                         (int)ATTN_SMEM);

    const int M = B_ * N_;  // 8192

    // 1) QKV projection
    gemm_tf32_kernel<<<dim3(QKV3 / 128, M / 256), 256, GEMM_SMEM>>>(
        x, Wqkv, qkv, M, QKV3, DIM_);
    // 2) Shuffled-Q attention (perm gather fused into Q load)
    attn_kernel<<<dim3(B_ * HEADS, N_ / 128), 256, ATTN_SMEM>>>(qkv, perm, att);
    // 3) Output projection
    gemm_tf32_kernel<<<dim3(INNER / 128, M / 256), 256, GEMM_SMEM>>>(
        att, Wout, out, M, INNER, DIM_);
}

// round 12
// speedup vs baseline: 2.0338x; 1.0018x over previous
#include <cuda_runtime.h>
#include <cuda_bf16.h>
#include <cstdint>
#include <cstddef>

// Problem constants
#define B_    8
#define N_    1024
#define DIM_  768
#define HEADS 12
#define DH    64
#define INNER 768          // HEADS*DH
#define QKV3  2304         // 3*INNER
#define SCALE 0.125f       // DH^-0.5

// Scratch (device globals: allocation-free rule)
__device__ float g_qkv[(size_t)B_ * N_ * QKV3];   // [b, n, 3*inner] (tf32-rounded)
__device__ float g_att[(size_t)B_ * N_ * INNER];  // [b, n, h*DH+d]  (tf32-rounded)
__device__ float g_x[(size_t)B_ * N_ * DIM_];     // tf32-rounded x
__device__ float g_wqkv[(size_t)DIM_ * QKV3];     // tf32-rounded W_qkv
__device__ float g_wout[(size_t)INNER * DIM_];    // tf32-rounded W_out

// ---------------------------------------------------------------------------
// tf32 + cp.async helpers
// ---------------------------------------------------------------------------
__device__ __forceinline__ uint32_t f2tf32(float x) {
    uint32_t u;
    asm("cvt.rna.tf32.f32 %0, %1;" : "=r"(u) : "f"(x));
    return u;
}
__device__ __forceinline__ float f2tf32f(float x) {
    return __uint_as_float(f2tf32(x));
}

__device__ __forceinline__ void cp_async16(void* smem_dst, const void* gmem_src) {
    uint32_t s = (uint32_t)__cvta_generic_to_shared(smem_dst);
    asm volatile("cp.async.cg.shared.global [%0], [%1], 16;\n"
                 :: "r"(s), "l"(gmem_src));
}
#define CP_COMMIT() asm volatile("cp.async.commit_group;\n" ::)
#define CP_WAIT(n)  asm volatile("cp.async.wait_group %0;\n" :: "n"(n))

__device__ __forceinline__ void mma_tf32(float c[4], const uint32_t a[4],
                                         uint32_t b0, uint32_t b1) {
    asm volatile(
        "mma.sync.aligned.m16n8k8.row.col.f32.tf32.tf32.f32 "
        "{%0,%1,%2,%3}, {%4,%5,%6,%7}, {%8,%9}, {%0,%1,%2,%3};"
        : "+f"(c[0]), "+f"(c[1]), "+f"(c[2]), "+f"(c[3])
        : "r"(a[0]), "r"(a[1]), "r"(a[2]), "r"(a[3]), "r"(b0), "r"(b1));
}

// ---------------------------------------------------------------------------
// Pre-pass: round fp32 buffer to tf32 values (RNA), elementwise float4.
// ---------------------------------------------------------------------------
__global__ __launch_bounds__(256) void round_tf32_kernel(
    const float4* __restrict__ in, float4* __restrict__ out, int n4)
{
    int i = blockIdx.x * blockDim.x + threadIdx.x;
    if (i < n4) {
        float4 v = in[i];
        out[i] = make_float4(f2tf32f(v.x), f2tf32f(v.y),
                             f2tf32f(v.z), f2tf32f(v.w));
    }
}

// ---------------------------------------------------------------------------
// tf32 GEMM, cp.async double-buffered. C[M,N] = A[M,K]*B[K,N].
// Inputs MUST be pre-rounded to tf32 values. If round_c, C is tf32-rounded.
// Block 256 thr (8 warps, 4x2), tile 256x128x32, warp tile 64x64.
// As[m][k] stride 36, Bs[k][n] stride 136 (conflict-free reads).
// ---------------------------------------------------------------------------
#define ASTR 36
#define BSTR 136
#define GSTAGE (256 * ASTR + 32 * BSTR)                     // floats per stage
#define GEMM_SMEM (2 * GSTAGE * sizeof(float))              // 108544 B

__global__ __launch_bounds__(256, 1) void gemm_tf32_kernel(
    const float* __restrict__ A, const float* __restrict__ Bm,
    float* __restrict__ C, int M, int N, int K, int round_c)
{
    extern __shared__ float gsm[];

    const int tid = threadIdx.x;
    const int warpid = tid >> 5;
    const int lane = tid & 31;
    const int g   = lane >> 2;
    const int tig = lane & 3;

    const int row0 = blockIdx.y * 256;
    const int col0 = blockIdx.x * 128;
    const int wm = (warpid >> 1) * 64;   // 4 m-warps
    const int wn = (warpid & 1) * 64;    // 2 n-warps

    float acc[4][8][4];
    #pragma unroll
    for (int mi = 0; mi < 4; mi++)
        #pragma unroll
        for (int j = 0; j < 8; j++)
            #pragma unroll
            for (int r = 0; r < 4; r++) acc[mi][j][r] = 0.f;

    auto load_tile = [&](int st, int k0) {
        float* As = gsm + st * GSTAGE;
        float* Bs = As + 256 * ASTR;
        #pragma unroll
        for (int i = 0; i < 8; i++) {
            int idx = tid + i * 256;
            int r = idx >> 3, cg = idx & 7;
            cp_async16(&As[r * ASTR + cg * 4],
                       &A[(size_t)(row0 + r) * K + k0 + cg * 4]);
        }
        #pragma unroll
        for (int i = 0; i < 4; i++) {
            int idx = tid + i * 256;
            int r = idx >> 5, cg = idx & 31;
            cp_async16(&Bs[r * BSTR + cg * 4],
                       &Bm[(size_t)(k0 + r) * N + col0 + cg * 4]);
        }
    };

    const int nkt = K / 32;
    load_tile(0, 0);
    CP_COMMIT();

    for (int kt = 0; kt < nkt; kt++) {
        int cur = kt & 1;
        if (kt + 1 < nkt) {
            load_tile(cur ^ 1, (kt + 1) * 32);
            CP_COMMIT();
            CP_WAIT(1);
        } else {
            CP_WAIT(0);
        }
        __syncthreads();

        const float* As = gsm + cur * GSTAGE;
        const float* Bs = As + 256 * ASTR;

        #pragma unroll
        for (int kc = 0; kc < 4; kc++) {
            uint32_t a[4][4];
            #pragma unroll
            for (int mi = 0; mi < 4; mi++) {
                int r = wm + mi * 16 + g;
                a[mi][0] = __float_as_uint(As[r * ASTR + kc * 8 + tig]);
                a[mi][1] = __float_as_uint(As[(r + 8) * ASTR + kc * 8 + tig]);
                a[mi][2] = __float_as_uint(As[r * ASTR + kc * 8 + tig + 4]);
                a[mi][3] = __float_as_uint(As[(r + 8) * ASTR + kc * 8 + tig + 4]);
            }
            #pragma unroll
            for (int j = 0; j < 8; j++) {
                uint32_t b0 = __float_as_uint(Bs[(kc * 8 + tig) * BSTR + wn + j * 8 + g]);
                uint32_t b1 = __float_as_uint(Bs[(kc * 8 + tig + 4) * BSTR + wn + j * 8 + g]);
                #pragma unroll
                for (int mi = 0; mi < 4; mi++)
                    mma_tf32(acc[mi][j], a[mi], b0, b1);
            }
        }
        __syncthreads();   // all reads of 'cur' done before it is refilled
    }

    // Writeback (optionally tf32-rounded for downstream consumers)
    #pragma unroll
    for (int mi = 0; mi < 4; mi++) {
        int r0 = row0 + wm + mi * 16 + g;
        #pragma unroll
        for (int j = 0; j < 8; j++) {
            int col = col0 + wn + j * 8 + 2 * tig;
            float v00 = acc[mi][j][0], v01 = acc[mi][j][1];
            float v10 = acc[mi][j][2], v11 = acc[mi][j][3];
            if (round_c) {
                v00 = f2tf32f(v00); v01 = f2tf32f(v01);
                v10 = f2tf32f(v10); v11 = f2tf32f(v11);
            }
            *(float2*)&C[(size_t)r0 * N + col] = make_float2(v00, v01);
            *(float2*)&C[(size_t)(r0 + 8) * N + col] = make_float2(v10, v11);
        }
    }
}

// ---------------------------------------------------------------------------
// Fused shuffled-Q flash attention, tf32 MMA, cp.async double-buffered K/V.
// qkv is pre-rounded tf32 -> no conversions in the copy path.
// Block 256 thr (8 warps), q-tile 128 rows (16/warp), K/V tiles 64 keys.
// Grid: (B*HEADS, N/128). Output written tf32-rounded.
// ---------------------------------------------------------------------------
#define AST 68
// Qs staging 128*AST, then K/V stages: 4 * 64*AST
#define ATTN_SMEM ((128 * AST + 4 * 64 * AST) * sizeof(float))   // 104448 B

__global__ __launch_bounds__(256) void attn_kernel(
    const float* __restrict__ qkv, const int* __restrict__ perm,
    float* __restrict__ out)
{
    extern __shared__ float sm[];
    float* Qs = sm;                       // [128][AST]; later aliased as Ps
    float* Ps = Qs;

    const int bh = blockIdx.x;
    const int b  = bh / HEADS, h = bh % HEADS;
    const int qt = blockIdx.y;
    const int tid = threadIdx.x;
    const int w    = tid >> 5;
    const int lane = tid & 31;
    const int g   = lane >> 2;
    const int tig = lane & 3;
    const int wq  = w * 16;

    const float* base = qkv + (size_t)b * N_ * QKV3;

    auto load_kv = [&](int st, int kt) {
        float* Ks = sm + 128 * AST + st * (2 * 64 * AST);
        float* Vs = Ks + 64 * AST;
        #pragma unroll
        for (int i = 0; i < 4; i++) {
            int idx = tid + i * 256;        // 0..1023 float4 slots
            int key = idx >> 4, d4 = idx & 15;
            const float* rowp = base + (size_t)(kt * 64 + key) * QKV3 + h * DH;
            cp_async16(&Ks[key * AST + d4 * 4], rowp + INNER + d4 * 4);
            cp_async16(&Vs[key * AST + d4 * 4], rowp + 2 * INNER + d4 * 4);
        }
    };

    // Kick off K/V tile 0 first, overlap with the Q gather.
    load_kv(0, 0);
    CP_COMMIT();

    // ---- Stage shuffled Q tile (perm gather; values already tf32) ----
    #pragma unroll
    for (int i = 0; i < 32; i++) {
        int idx = tid + i * 256;            // 0..8191
        int r = idx >> 6, d = idx & 63;
        int p  = perm[((qt * 128 + r) << 6) + d];
        int n2 = p >> 6, d2 = p & 63;
        Qs[r * AST + d] = base[(size_t)n2 * QKV3 + h * DH + d2];
    }
    __syncthreads();

    // ---- Cache Q fragments in registers (whole key loop) ----
    uint32_t qa[8][4];
    #pragma unroll
    for (int kc = 0; kc < 8; kc++) {
        int r = wq + g;
        qa[kc][0] = __float_as_uint(Qs[r * AST + kc * 8 + tig]);
        qa[kc][1] = __float_as_uint(Qs[(r + 8) * AST + kc * 8 + tig]);
        qa[kc][2] = __float_as_uint(Qs[r * AST + kc * 8 + tig + 4]);
        qa[kc][3] = __float_as_uint(Qs[(r + 8) * AST + kc * 8 + tig + 4]);
    }

    float o[8][4];
    #pragma unroll
    for (int j = 0; j < 8; j++)
        #pragma unroll
        for (int r = 0; r < 4; r++) o[j][r] = 0.f;
    float m0 = -1e30f, m1 = -1e30f, l0 = 0.f, l1 = 0.f;

    const int nkt = N_ / 64;
    for (int kt = 0; kt < nkt; kt++) {
        int cur = kt & 1;
        if (kt + 1 < nkt) {
            load_kv(cur ^ 1, kt + 1);
            CP_COMMIT();
            CP_WAIT(1);
        } else {
            CP_WAIT(0);
        }
        __syncthreads();

        const float* Ks = sm + 128 * AST + cur * (2 * 64 * AST);
        const float* Vs = Ks + 64 * AST;

        // ---- S = Q K^T : m16 x n64, 8 k8-steps, A from registers ----
        float s[8][4];
        #pragma unroll
        for (int j = 0; j < 8; j++)
            #pragma unroll
            for (int r = 0; r < 4; r++) s[j][r] = 0.f;
        #pragma unroll
        for (int kc = 0; kc < 8; kc++) {
            #pragma unroll
            for (int j = 0; j < 8; j++) {
                uint32_t b0 = __float_as_uint(Ks[(j * 8 + g) * AST + kc * 8 + tig]);
                uint32_t b1 = __float_as_uint(Ks[(j * 8 + g) * AST + kc * 8 + tig + 4]);
                mma_tf32(s[j], qa[kc], b0, b1);
            }
        }

        // ---- Online softmax (rows g / g+8 within warp's 16) ----
        float mx0 = -1e30f, mx1 = -1e30f;
        #pragma unroll
        for (int j = 0; j < 8; j++) {
            s[j][0] *= SCALE; s[j][1] *= SCALE; s[j][2] *= SCALE; s[j][3] *= SCALE;
            mx0 = fmaxf(mx0, fmaxf(s[j][0], s[j][1]));
            mx1 = fmaxf(mx1, fmaxf(s[j][2], s[j][3]));
        }
        mx0 = fmaxf(mx0, __shfl_xor_sync(0xffffffffu, mx0, 1));
        mx0 = fmaxf(mx0, __shfl_xor_sync(0xffffffffu, mx0, 2));
        mx1 = fmaxf(mx1, __shfl_xor_sync(0xffffffffu, mx1, 1));
        mx1 = fmaxf(mx1, __shfl_xor_sync(0xffffffffu, mx1, 2));

        float nm0 = fmaxf(m0, mx0), nm1 = fmaxf(m1, mx1);
        float al0 = __expf(m0 - nm0), al1 = __expf(m1 - nm1);
        float rs0 = 0.f, rs1 = 0.f;
        #pragma unroll
        for (int j = 0; j < 8; j++) {
            s[j][0] = __expf(s[j][0] - nm0);
            s[j][1] = __expf(s[j][1] - nm0);
            s[j][2] = __expf(s[j][2] - nm1);
            s[j][3] = __expf(s[j][3] - nm1);
            rs0 += s[j][0] + s[j][1];
            rs1 += s[j][2] + s[j][3];
            int pr = wq + g;
            int pc = j * 8 + 2 * tig;
            *(float2*)&Ps[pr * AST + pc] = make_float2(
                f2tf32f(s[j][0]), f2tf32f(s[j][1]));
            *(float2*)&Ps[(pr + 8) * AST + pc] = make_float2(
                f2tf32f(s[j][2]), f2tf32f(s[j][3]));
        }
        rs0 += __shfl_xor_sync(0xffffffffu, rs0, 1);
        rs0 += __shfl_xor_sync(0xffffffffu, rs0, 2);
        rs1 += __shfl_xor_sync(0xffffffffu, rs1, 1);
        rs1 += __shfl_xor_sync(0xffffffffu, rs1, 2);
        l0 = l0 * al0 + rs0; l1 = l1 * al1 + rs1;
        m0 = nm0; m1 = nm1;
        #pragma unroll
        for (int j = 0; j < 8; j++) {
            o[j][0] *= al0; o[j][1] *= al0; o[j][2] *= al1; o[j][3] *= al1;
        }
        __syncwarp();   // Ps rows are warp-private (wq..wq+15)

        // ---- O += P V : m16 x n64, 8 k8-steps ----
        #pragma unroll
        for (int kc = 0; kc < 8; kc++) {
            uint32_t pa[4];
            int r = wq + g;
            pa[0] = __float_as_uint(Ps[r * AST + kc * 8 + tig]);
            pa[1] = __float_as_uint(Ps[(r + 8) * AST + kc * 8 + tig]);
            pa[2] = __float_as_uint(Ps[r * AST + kc * 8 + tig + 4]);
            pa[3] = __float_as_uint(Ps[(r + 8) * AST + kc * 8 + tig + 4]);
            #pragma unroll
            for (int j = 0; j < 8; j++) {
                uint32_t b0 = __float_as_uint(Vs[(kc * 8 + tig) * AST + j * 8 + g]);
                uint32_t b1 = __float_as_uint(Vs[(kc * 8 + tig + 4) * AST + j * 8 + g]);
                mma_tf32(o[j], pa, b0, b1);
            }
        }
        __syncthreads();   // all reads of 'cur' K/V done before refill
    }

    // ---- Normalize + write out[b, q, h*DH + d] (tf32-rounded) ----
    float inv0 = 1.0f / l0, inv1 = 1.0f / l1;
    int q0 = qt * 128 + wq + g;
    #pragma unroll
    for (int j = 0; j < 8; j++) {
        int d = j * 8 + 2 * tig;
        size_t o0 = ((size_t)b * N_ + q0) * INNER + h * DH + d;
        size_t o1 = ((size_t)b * N_ + q0 + 8) * INNER + h * DH + d;
        *(float2*)&out[o0] = make_float2(f2tf32f(o[j][0] * inv0),
                                         f2tf32f(o[j][1] * inv0));
        *(float2*)&out[o1] = make_float2(f2tf32f(o[j][2] * inv1),
                                         f2tf32f(o[j][3] * inv1));
    }
}

// ---------------------------------------------------------------------------
// Launch
// ---------------------------------------------------------------------------
extern "C" void kernel_launch(void* const* d_in, const int* in_sizes, int n_in,
                              void* d_out, int out_size)
{
    const float* x    = (const float*)d_in[0];   // [8,1024,768]
    const float* Wqkv = (const float*)d_in[1];   // [768,2304]
    const float* Wout = (const float*)d_in[2];   // [768,768]
    const int*   perm = (const int*)d_in[3];     // [65536]
    float* out = (float*)d_out;

    float *qkv, *att, *xr, *wqkvr, *woutr;
    cudaGetSymbolAddress((void**)&qkv, g_qkv);
    cudaGetSymbolAddress((void**)&att, g_att);
    cudaGetSymbolAddress((void**)&xr, g_x);
    cudaGetSymbolAddress((void**)&wqkvr, g_wqkv);
    cudaGetSymbolAddress((void**)&woutr, g_wout);
    cudaFuncSetAttribute(gemm_tf32_kernel,
                         cudaFuncAttributeMaxDynamicSharedMemorySize,
                         (int)GEMM_SMEM);
    cudaFuncSetAttribute(attn_kernel,
                         cudaFuncAttributeMaxDynamicSharedMemorySize,
                         (int)ATTN_SMEM);

    const int M = B_ * N_;  // 8192

    // 0) Pre-round inputs to tf32 (RNA) once; hot loops become pure copies.
    {
        int n4x = (B_ * N_ * DIM_) / 4;
        int n4q = (DIM_ * QKV3) / 4;
        int n4o = (INNER * DIM_) / 4;
        round_tf32_kernel<<<(n4x + 255) / 256, 256>>>((const float4*)x, (float4*)xr, n4x);
        round_tf32_kernel<<<(n4q + 255) / 256, 256>>>((const float4*)Wqkv, (float4*)wqkvr, n4q);
        round_tf32_kernel<<<(n4o + 255) / 256, 256>>>((const float4*)Wout, (float4*)woutr, n4o);
    }

    // 1) QKV projection (writes tf32-rounded qkv)
    gemm_tf32_kernel<<<dim3(QKV3 / 128, M / 256), 256, GEMM_SMEM>>>(
        xr, wqkvr, qkv, M, QKV3, DIM_, 1);
    // 2) Shuffled-Q attention (perm gather fused; writes tf32-rounded att)
    attn_kernel<<<dim3(B_ * HEADS, N_ / 128), 256, ATTN_SMEM>>>(qkv, perm, att);
    // 3) Output projection (final output: NOT rounded)
    gemm_tf32_kernel<<<dim3(INNER / 128, M / 256), 256, GEMM_SMEM>>>(
        att, woutr, out, M, INNER, DIM_, 0);
}

// round 13
// speedup vs baseline: 2.3501x; 1.1555x over previous
#include <cuda_runtime.h>
#include <cuda_bf16.h>
#include <cstdint>
#include <cstddef>

// Problem constants
#define B_    8
#define N_    1024
#define DIM_  768
#define HEADS 12
#define DH    64
#define INNER 768          // HEADS*DH
#define QKV3  2304         // 3*INNER
#define SCALE 0.125f       // DH^-0.5

// Scratch (device globals: allocation-free rule)
__device__ float g_qkv[(size_t)B_ * N_ * QKV3];   // tf32-rounded qkv
__device__ float g_att[(size_t)B_ * N_ * INNER];  // tf32-rounded attn out
__device__ float g_x[(size_t)B_ * N_ * DIM_];     // tf32-rounded x
__device__ float g_wqkv[(size_t)DIM_ * QKV3];     // tf32-rounded W_qkv
__device__ float g_wout[(size_t)INNER * DIM_];    // tf32-rounded W_out

// ---------------------------------------------------------------------------
// tf32 + cp.async helpers
// ---------------------------------------------------------------------------
__device__ __forceinline__ uint32_t f2tf32(float x) {
    uint32_t u;
    asm("cvt.rna.tf32.f32 %0, %1;" : "=r"(u) : "f"(x));
    return u;
}
__device__ __forceinline__ float f2tf32f(float x) {
    return __uint_as_float(f2tf32(x));
}

__device__ __forceinline__ void cp_async16(void* smem_dst, const void* gmem_src) {
    uint32_t s = (uint32_t)__cvta_generic_to_shared(smem_dst);
    asm volatile("cp.async.cg.shared.global [%0], [%1], 16;\n"
                 :: "r"(s), "l"(gmem_src));
}
#define CP_COMMIT() asm volatile("cp.async.commit_group;\n" ::)
#define CP_WAIT(n)  asm volatile("cp.async.wait_group %0;\n" :: "n"(n))

__device__ __forceinline__ void mma_tf32(float c[4], const uint32_t a[4],
                                         uint32_t b0, uint32_t b1) {
    asm volatile(
        "mma.sync.aligned.m16n8k8.row.col.f32.tf32.tf32.f32 "
        "{%0,%1,%2,%3}, {%4,%5,%6,%7}, {%8,%9}, {%0,%1,%2,%3};"
        : "+f"(c[0]), "+f"(c[1]), "+f"(c[2]), "+f"(c[3])
        : "r"(a[0]), "r"(a[1]), "r"(a[2]), "r"(a[3]), "r"(b0), "r"(b1));
}

// ---------------------------------------------------------------------------
// Pre-pass: round fp32 buffer to tf32 values (RNA), elementwise float4.
// ---------------------------------------------------------------------------
__global__ __launch_bounds__(256) void round_tf32_kernel(
    const float4* __restrict__ in, float4* __restrict__ out, int n4)
{
    int i = blockIdx.x * blockDim.x + threadIdx.x;
    if (i < n4) {
        float4 v = in[i];
        out[i] = make_float4(f2tf32f(v.x), f2tf32f(v.y),
                             f2tf32f(v.z), f2tf32f(v.w));
    }
}

// ---------------------------------------------------------------------------
// tf32 GEMM, cp.async double-buffered. C[M,N] = A[M,K]*B[K,N].
// Block 128 thr (4 warps, 2x2), tile 128x128x32, warp tile 64x64.
// 2 blocks/SM expected (71.7 KB smem, ~240 regs).
// As[m][k] stride 36, Bs[k][n] stride 136 (conflict-free reads).
// ---------------------------------------------------------------------------
#define ASTR 36
#define BSTR 136
#define GSTAGE (128 * ASTR + 32 * BSTR)                     // floats per stage
#define GEMM_SMEM (2 * GSTAGE * sizeof(float))              // 71680 B

__global__ __launch_bounds__(128) void gemm_tf32_kernel(
    const float* __restrict__ A, const float* __restrict__ Bm,
    float* __restrict__ C, int M, int N, int K, int round_c)
{
    extern __shared__ float gsm[];

    const int tid = threadIdx.x;
    const int warpid = tid >> 5;
    const int lane = tid & 31;
    const int g   = lane >> 2;
    const int tig = lane & 3;

    const int row0 = blockIdx.y * 128;
    const int col0 = blockIdx.x * 128;
    const int wm = (warpid >> 1) * 64;   // 2 m-warps
    const int wn = (warpid & 1) * 64;    // 2 n-warps

    float acc[4][8][4];
    #pragma unroll
    for (int mi = 0; mi < 4; mi++)
        #pragma unroll
        for (int j = 0; j < 8; j++)
            #pragma unroll
            for (int r = 0; r < 4; r++) acc[mi][j][r] = 0.f;

    auto load_tile = [&](int st, int k0) {
        float* As = gsm + st * GSTAGE;
        float* Bs = As + 128 * ASTR;
        // A tile 128x32: 1024 float4, 8 per thread
        #pragma unroll
        for (int i = 0; i < 8; i++) {
            int idx = tid + i * 128;
            int r = idx >> 3, cg = idx & 7;
            cp_async16(&As[r * ASTR + cg * 4],
                       &A[(size_t)(row0 + r) * K + k0 + cg * 4]);
        }
        // B tile 32x128: 1024 float4, 8 per thread
        #pragma unroll
        for (int i = 0; i < 8; i++) {
            int idx = tid + i * 128;
            int r = idx >> 5, cg = idx & 31;
            cp_async16(&Bs[r * BSTR + cg * 4],
                       &Bm[(size_t)(k0 + r) * N + col0 + cg * 4]);
        }
    };

    const int nkt = K / 32;
    load_tile(0, 0);
    CP_COMMIT();

    for (int kt = 0; kt < nkt; kt++) {
        int cur = kt & 1;
        if (kt + 1 < nkt) {
            load_tile(cur ^ 1, (kt + 1) * 32);
            CP_COMMIT();
            CP_WAIT(1);
        } else {
            CP_WAIT(0);
        }
        __syncthreads();

        const float* As = gsm + cur * GSTAGE;
        const float* Bs = As + 128 * ASTR;

        #pragma unroll
        for (int kc = 0; kc < 4; kc++) {
            uint32_t a[4][4];
            #pragma unroll
            for (int mi = 0; mi < 4; mi++) {
                int r = wm + mi * 16 + g;
                a[mi][0] = __float_as_uint(As[r * ASTR + kc * 8 + tig]);
                a[mi][1] = __float_as_uint(As[(r + 8) * ASTR + kc * 8 + tig]);
                a[mi][2] = __float_as_uint(As[r * ASTR + kc * 8 + tig + 4]);
                a[mi][3] = __float_as_uint(As[(r + 8) * ASTR + kc * 8 + tig + 4]);
            }
            #pragma unroll
            for (int j = 0; j < 8; j++) {
                uint32_t b0 = __float_as_uint(Bs[(kc * 8 + tig) * BSTR + wn + j * 8 + g]);
                uint32_t b1 = __float_as_uint(Bs[(kc * 8 + tig + 4) * BSTR + wn + j * 8 + g]);
                #pragma unroll
                for (int mi = 0; mi < 4; mi++)
                    mma_tf32(acc[mi][j], a[mi], b0, b1);
            }
        }
        __syncthreads();   // all reads of 'cur' done before it is refilled
    }

    // Writeback (optionally tf32-rounded for downstream consumers)
    #pragma unroll
    for (int mi = 0; mi < 4; mi++) {
        int r0 = row0 + wm + mi * 16 + g;
        #pragma unroll
        for (int j = 0; j < 8; j++) {
            int col = col0 + wn + j * 8 + 2 * tig;
            float v00 = acc[mi][j][0], v01 = acc[mi][j][1];
            float v10 = acc[mi][j][2], v11 = acc[mi][j][3];
            if (round_c) {
                v00 = f2tf32f(v00); v01 = f2tf32f(v01);
                v10 = f2tf32f(v10); v11 = f2tf32f(v11);
            }
            *(float2*)&C[(size_t)r0 * N + col] = make_float2(v00, v01);
            *(float2*)&C[(size_t)(r0 + 8) * N + col] = make_float2(v10, v11);
        }
    }
}

// ---------------------------------------------------------------------------
// Fused shuffled-Q flash attention, tf32 MMA, cp.async double-buffered K/V.
// Block 128 thr (4 warps), q-tile 64 rows (16/warp), K/V tiles 64 keys.
// 2 blocks/SM expected (87 KB smem). Grid: (B*HEADS, N/64).
// ---------------------------------------------------------------------------
#define AST 68
// Qs staging 64*AST, then 2 K/V stages: 4 * 64*AST
#define ATTN_SMEM ((64 * AST + 4 * 64 * AST) * sizeof(float))   // 87040 B

__global__ __launch_bounds__(128) void attn_kernel(
    const float* __restrict__ qkv, const int* __restrict__ perm,
    float* __restrict__ out)
{
    extern __shared__ float sm[];
    float* Qs = sm;                       // [64][AST]; later aliased as Ps
    float* Ps = Qs;

    const int bh = blockIdx.x;
    const int b  = bh / HEADS, h = bh % HEADS;
    const int qt = blockIdx.y;
    const int tid = threadIdx.x;
    const int w    = tid >> 5;
    const int lane = tid & 31;
    const int g   = lane >> 2;
    const int tig = lane & 3;
    const int wq  = w * 16;

    const float* base = qkv + (size_t)b * N_ * QKV3;

    auto load_kv = [&](int st, int kt) {
        float* Ks = sm + 64 * AST + st * (2 * 64 * AST);
        float* Vs = Ks + 64 * AST;
        #pragma unroll
        for (int i = 0; i < 8; i++) {
            int idx = tid + i * 128;        // 0..1023 float4 slots
            int key = idx >> 4, d4 = idx & 15;
            const float* rowp = base + (size_t)(kt * 64 + key) * QKV3 + h * DH;
            cp_async16(&Ks[key * AST + d4 * 4], rowp + INNER + d4 * 4);
            cp_async16(&Vs[key * AST + d4 * 4], rowp + 2 * INNER + d4 * 4);
        }
    };

    // Kick off K/V tile 0 first, overlap with the Q gather.
    load_kv(0, 0);
    CP_COMMIT();

    // ---- Stage shuffled Q tile (perm gather; values already tf32) ----
    #pragma unroll
    for (int i = 0; i < 32; i++) {
        int idx = tid + i * 128;            // 0..4095
        int r = idx >> 6, d = idx & 63;
        int p  = perm[((qt * 64 + r) << 6) + d];
        int n2 = p >> 6, d2 = p & 63;
        Qs[r * AST + d] = base[(size_t)n2 * QKV3 + h * DH + d2];
    }
    __syncthreads();

    // ---- Cache Q fragments in registers (whole key loop) ----
    uint32_t qa[8][4];
    #pragma unroll
    for (int kc = 0; kc < 8; kc++) {
        int r = wq + g;
        qa[kc][0] = __float_as_uint(Qs[r * AST + kc * 8 + tig]);
        qa[kc][1] = __float_as_uint(Qs[(r + 8) * AST + kc * 8 + tig]);
        qa[kc][2] = __float_as_uint(Qs[r * AST + kc * 8 + tig + 4]);
        qa[kc][3] = __float_as_uint(Qs[(r + 8) * AST + kc * 8 + tig + 4]);
    }

    float o[8][4];
    #pragma unroll
    for (int j = 0; j < 8; j++)
        #pragma unroll
        for (int r = 0; r < 4; r++) o[j][r] = 0.f;
    float m0 = -1e30f, m1 = -1e30f, l0 = 0.f, l1 = 0.f;

    const int nkt = N_ / 64;
    for (int kt = 0; kt < nkt; kt++) {
        int cur = kt & 1;
        if (kt + 1 < nkt) {
            load_kv(cur ^ 1, kt + 1);
            CP_COMMIT();
            CP_WAIT(1);
        } else {
            CP_WAIT(0);
        }
        __syncthreads();

        const float* Ks = sm + 64 * AST + cur * (2 * 64 * AST);
        const float* Vs = Ks + 64 * AST;

        // ---- S = Q K^T : m16 x n64, 8 k8-steps, A from registers ----
        float s[8][4];
        #pragma unroll
        for (int j = 0; j < 8; j++)
            #pragma unroll
            for (int r = 0; r < 4; r++) s[j][r] = 0.f;
        #pragma unroll
        for (int kc = 0; kc < 8; kc++) {
            #pragma unroll
            for (int j = 0; j < 8; j++) {
                uint32_t b0 = __float_as_uint(Ks[(j * 8 + g) * AST + kc * 8 + tig]);
                uint32_t b1 = __float_as_uint(Ks[(j * 8 + g) * AST + kc * 8 + tig + 4]);
                mma_tf32(s[j], qa[kc], b0, b1);
            }
        }

        // ---- Online softmax (rows g / g+8 within warp's 16) ----
        float mx0 = -1e30f, mx1 = -1e30f;
        #pragma unroll
        for (int j = 0; j < 8; j++) {
            s[j][0] *= SCALE; s[j][1] *= SCALE; s[j][2] *= SCALE; s[j][3] *= SCALE;
            mx0 = fmaxf(mx0, fmaxf(s[j][0], s[j][1]));
            mx1 = fmaxf(mx1, fmaxf(s[j][2], s[j][3]));
        }
        mx0 = fmaxf(mx0, __shfl_xor_sync(0xffffffffu, mx0, 1));
        mx0 = fmaxf(mx0, __shfl_xor_sync(0xffffffffu, mx0, 2));
        mx1 = fmaxf(mx1, __shfl_xor_sync(0xffffffffu, mx1, 1));
        mx1 = fmaxf(mx1, __shfl_xor_sync(0xffffffffu, mx1, 2));

        float nm0 = fmaxf(m0, mx0), nm1 = fmaxf(m1, mx1);
        float al0 = __expf(m0 - nm0), al1 = __expf(m1 - nm1);
        float rs0 = 0.f, rs1 = 0.f;
        #pragma unroll
        for (int j = 0; j < 8; j++) {
            s[j][0] = __expf(s[j][0] - nm0);
            s[j][1] = __expf(s[j][1] - nm0);
            s[j][2] = __expf(s[j][2] - nm1);
            s[j][3] = __expf(s[j][3] - nm1);
            rs0 += s[j][0] + s[j][1];
            rs1 += s[j][2] + s[j][3];
            int pr = wq + g;
            int pc = j * 8 + 2 * tig;
            *(float2*)&Ps[pr * AST + pc] = make_float2(
                f2tf32f(s[j][0]), f2tf32f(s[j][1]));
            *(float2*)&Ps[(pr + 8) * AST + pc] = make_float2(
                f2tf32f(s[j][2]), f2tf32f(s[j][3]));
        }
        rs0 += __shfl_xor_sync(0xffffffffu, rs0, 1);
        rs0 += __shfl_xor_sync(0xffffffffu, rs0, 2);
        rs1 += __shfl_xor_sync(0xffffffffu, rs1, 1);
        rs1 += __shfl_xor_sync(0xffffffffu, rs1, 2);
        l0 = l0 * al0 + rs0; l1 = l1 * al1 + rs1;
        m0 = nm0; m1 = nm1;
        #pragma unroll
        for (int j = 0; j < 8; j++) {
            o[j][0] *= al0; o[j][1] *= al0; o[j][2] *= al1; o[j][3] *= al1;
        }
        __syncwarp();   // Ps rows are warp-private (wq..wq+15)

        // ---- O += P V : m16 x n64, 8 k8-steps ----
        #pragma unroll
        for (int kc = 0; kc < 8; kc++) {
            uint32_t pa[4];
            int r = wq + g;
            pa[0] = __float_as_uint(Ps[r * AST + kc * 8 + tig]);
            pa[1] = __float_as_uint(Ps[(r + 8) * AST + kc * 8 + tig]);
            pa[2] = __float_as_uint(Ps[r * AST + kc * 8 + tig + 4]);
            pa[3] = __float_as_uint(Ps[(r + 8) * AST + kc * 8 + tig + 4]);
            #pragma unroll
            for (int j = 0; j < 8; j++) {
                uint32_t b0 = __float_as_uint(Vs[(kc * 8 + tig) * AST + j * 8 + g]);
                uint32_t b1 = __float_as_uint(Vs[(kc * 8 + tig + 4) * AST + j * 8 + g]);
                mma_tf32(o[j], pa, b0, b1);
            }
        }
        __syncthreads();   // all reads of 'cur' K/V done before refill
    }

    // ---- Normalize + write out[b, q, h*DH + d] (tf32-rounded) ----
    float inv0 = 1.0f / l0, inv1 = 1.0f / l1;
    int q0 = qt * 64 + wq + g;
    #pragma unroll
    for (int j = 0; j < 8; j++) {
        int d = j * 8 + 2 * tig;
        size_t o0 = ((size_t)b * N_ + q0) * INNER + h * DH + d;
        size_t o1 = ((size_t)b * N_ + q0 + 8) * INNER + h * DH + d;
        *(float2*)&out[o0] = make_float2(f2tf32f(o[j][0] * inv0),
                                         f2tf32f(o[j][1] * inv0));
        *(float2*)&out[o1] = make_float2(f2tf32f(o[j][2] * inv1),
                                         f2tf32f(o[j][3] * inv1));
    }
}

// ---------------------------------------------------------------------------
// Launch
// ---------------------------------------------------------------------------
extern "C" void kernel_launch(void* const* d_in, const int* in_sizes, int n_in,
                              void* d_out, int out_size)
{
    const float* x    = (const float*)d_in[0];   // [8,1024,768]
    const float* Wqkv = (const float*)d_in[1];   // [768,2304]
    const float* Wout = (const float*)d_in[2];   // [768,768]
    const int*   perm = (const int*)d_in[3];     // [65536]
    float* out = (float*)d_out;

    float *qkv, *att, *xr, *wqkvr, *woutr;
    cudaGetSymbolAddress((void**)&qkv, g_qkv);
    cudaGetSymbolAddress((void**)&att, g_att);
    cudaGetSymbolAddress((void**)&xr, g_x);
    cudaGetSymbolAddress((void**)&wqkvr, g_wqkv);
    cudaGetSymbolAddress((void**)&woutr, g_wout);
    cudaFuncSetAttribute(gemm_tf32_kernel,
                         cudaFuncAttributeMaxDynamicSharedMemorySize,
                         (int)GEMM_SMEM);
    cudaFuncSetAttribute(attn_kernel,
                         cudaFuncAttributeMaxDynamicSharedMemorySize,
                         (int)ATTN_SMEM);

    const int M = B_ * N_;  // 8192

    // 0) Pre-round inputs to tf32 (RNA) once; hot loops become pure copies.
    {
        int n4x = (B_ * N_ * DIM_) / 4;
        int n4q = (DIM_ * QKV3) / 4;
        int n4o = (INNER * DIM_) / 4;
        round_tf32_kernel<<<(n4x + 255) / 256, 256>>>((const float4*)x, (float4*)xr, n4x);
        round_tf32_kernel<<<(n4q + 255) / 256, 256>>>((const float4*)Wqkv, (float4*)wqkvr, n4q);
        round_tf32_kernel<<<(n4o + 255) / 256, 256>>>((const float4*)Wout, (float4*)woutr, n4o);
    }

    // 1) QKV projection (writes tf32-rounded qkv)
    gemm_tf32_kernel<<<dim3(QKV3 / 128, M / 128), 128, GEMM_SMEM>>>(
        xr, wqkvr, qkv, M, QKV3, DIM_, 1);
    // 2) Shuffled-Q attention (perm gather fused; writes tf32-rounded att)
    attn_kernel<<<dim3(B_ * HEADS, N_ / 64), 128, ATTN_SMEM>>>(qkv, perm, att);
    // 3) Output projection (final output: NOT rounded)
    gemm_tf32_kernel<<<dim3(INNER / 128, M / 128), 128, GEMM_SMEM>>>(
        att, woutr, out, M, INNER, DIM_, 0);
}